// round 16
// baseline (speedup 1.0000x reference)
#include <cuda_runtime.h>
#include <cuda_bf16.h>
#include <cuda_fp16.h>
#include <math.h>
#include <stdint.h>

#define HD   768
#define NHD  12
#define DHD  64
#define BB   4
#define SSQ  1024
#define EPSF 1e-6f
#define LOG2E 1.4426950408889634f

#define SWZ128(x) ((x) ^ (((x) >> 3) & 0x70))

__device__ __forceinline__ uint32_t smem_u32(const void* p) {
    uint32_t a;
    asm("{ .reg .u64 t; cvta.to.shared.u64 t, %1; cvt.u32.u64 %0, t; }" : "=r"(a) : "l"(p));
    return a;
}
__device__ __forceinline__ float ex2f(float x) {
    float r; asm("ex2.approx.f32 %0, %1;" : "=f"(r) : "f"(x)); return r;
}

#define LDSM4(r, addr) \
    asm volatile("ldmatrix.sync.aligned.m8n8.x4.shared.b16 {%0,%1,%2,%3}, [%4];" \
        : "=r"((r)[0]), "=r"((r)[1]), "=r"((r)[2]), "=r"((r)[3]) : "r"(addr))

#define MMA_BF16(d, a, b0, b1) \
    asm volatile("mma.sync.aligned.m16n8k16.row.col.f32.bf16.bf16.f32 " \
        "{%0,%1,%2,%3}, {%4,%5,%6,%7}, {%8,%9}, {%0,%1,%2,%3};" \
        : "+f"((d)[0]), "+f"((d)[1]), "+f"((d)[2]), "+f"((d)[3]) \
        : "r"((a)[0]), "r"((a)[1]), "r"((a)[2]), "r"((a)[3]), "r"(b0), "r"(b1))

#define MMA_F16(d, a, b0, b1) \
    asm volatile("mma.sync.aligned.m16n8k16.row.col.f32.f16.f16.f32 " \
        "{%0,%1,%2,%3}, {%4,%5,%6,%7}, {%8,%9}, {%0,%1,%2,%3};" \
        : "+f"((d)[0]), "+f"((d)[1]), "+f"((d)[2]), "+f"((d)[3]) \
        : "r"((a)[0]), "r"((a)[1]), "r"((a)[2]), "r"((a)[3]), "r"(b0), "r"(b1))

__device__ __forceinline__ void cp16(uint32_t d, const void* s) {
    asm volatile("cp.async.cg.shared.global [%0], [%1], 16;" :: "r"(d), "l"(s) : "memory");
}
#define CP_COMMIT() asm volatile("cp.async.commit_group;" ::: "memory")
#define CP_WAIT(n)  asm volatile("cp.async.wait_group %0;" :: "n"(n) : "memory")

// ---------------------------------------------------------------------------
// Scratch (allocation-free rule: __device__ globals)
// ---------------------------------------------------------------------------
__device__ __half g_q16[BB*NHD*SSQ*DHD];   // q fp16 [bh][tok][dim]
__device__ __half g_k16[BB*NHD*SSQ*DHD];
__device__ __half g_t16[BB*NHD*SSQ*DHD];
__device__ __half g_s16[BB*NHD*SSQ*DHD];
__device__ __half g_vT16[BB*NHD*DHD*SSQ];  // V fp16 [bh][dim][tok]
__device__ float g_itn[BB*NHD*SSQ];
__device__ float g_isn[BB*NHD*SSQ];

// bf16 split-precision GEMM inputs
__device__ __nv_bfloat16 g_xh[3*BB*SSQ*HD];
__device__ __nv_bfloat16 g_xl[3*BB*SSQ*HD];
__device__ __nv_bfloat16 g_wh[5*HD*HD];
__device__ __nv_bfloat16 g_wl[5*HD*HD];

// ---------------------------------------------------------------------------
// fp32 -> bf16 hi/lo split kernels
// ---------------------------------------------------------------------------
__global__ __launch_bounds__(256) void split_x_kernel(
    const float* __restrict__ hs, const float* __restrict__ te, const float* __restrict__ se)
{
    const float* src = (blockIdx.y == 0) ? hs : (blockIdx.y == 1) ? te : se;
    const size_t off = (size_t)blockIdx.y * (size_t)(BB*SSQ*HD);
    size_t i = ((size_t)blockIdx.x * blockDim.x + threadIdx.x) * 4;
    if (i >= (size_t)(BB*SSQ*HD)) return;
    float4 x = *(const float4*)(src + i);
    __nv_bfloat16 h0 = __float2bfloat16(x.x), h1 = __float2bfloat16(x.y);
    __nv_bfloat16 h2 = __float2bfloat16(x.z), h3 = __float2bfloat16(x.w);
    __nv_bfloat162 hA; hA.x = h0; hA.y = h1;
    __nv_bfloat162 hB; hB.x = h2; hB.y = h3;
    __nv_bfloat162 lA; lA.x = __float2bfloat16(x.x - __bfloat162float(h0));
                       lA.y = __float2bfloat16(x.y - __bfloat162float(h1));
    __nv_bfloat162 lB; lB.x = __float2bfloat16(x.z - __bfloat162float(h2));
                       lB.y = __float2bfloat16(x.w - __bfloat162float(h3));
    *(__nv_bfloat162*)(g_xh + off + i)     = hA;
    *(__nv_bfloat162*)(g_xh + off + i + 2) = hB;
    *(__nv_bfloat162*)(g_xl + off + i)     = lA;
    *(__nv_bfloat162*)(g_xl + off + i + 2) = lB;
}

__global__ __launch_bounds__(256) void split_w_kernel(
    const float* __restrict__ Wq, const float* __restrict__ Wk, const float* __restrict__ Wv,
    const float* __restrict__ Wt, const float* __restrict__ Ws)
{
    const int z = blockIdx.y;
    const float* src = (z==0)?Wq:(z==1)?Wk:(z==2)?Wv:(z==3)?Wt:Ws;
    const size_t off = (size_t)z * (size_t)(HD*HD);
    size_t i = ((size_t)blockIdx.x * blockDim.x + threadIdx.x) * 4;
    if (i >= (size_t)(HD*HD)) return;
    float4 x = *(const float4*)(src + i);
    __nv_bfloat16 h0 = __float2bfloat16(x.x), h1 = __float2bfloat16(x.y);
    __nv_bfloat16 h2 = __float2bfloat16(x.z), h3 = __float2bfloat16(x.w);
    __nv_bfloat162 hA; hA.x = h0; hA.y = h1;
    __nv_bfloat162 hB; hB.x = h2; hB.y = h3;
    __nv_bfloat162 lA; lA.x = __float2bfloat16(x.x - __bfloat162float(h0));
                       lA.y = __float2bfloat16(x.y - __bfloat162float(h1));
    __nv_bfloat162 lB; lB.x = __float2bfloat16(x.z - __bfloat162float(h2));
                       lB.y = __float2bfloat16(x.w - __bfloat162float(h3));
    *(__nv_bfloat162*)(g_wh + off + i)     = hA;
    *(__nv_bfloat162*)(g_wh + off + i + 2) = hB;
    *(__nv_bfloat162*)(g_wl + off + i)     = lA;
    *(__nv_bfloat162*)(g_wl + off + i + 2) = lB;
}

// ---------------------------------------------------------------------------
// HMMA projection GEMM (split hh+hl+lh), cp.async 3-stage pipeline.  (unchanged)
// ---------------------------------------------------------------------------
#define PSTAGE     65536
#define PROJ_SMEM  (3*PSTAGE)

__global__ __launch_bounds__(256) void proj_hmma_kernel(
    const float* __restrict__ bq, const float* __restrict__ bk,
    const float* __restrict__ bv, const float* __restrict__ bt,
    const float* __restrict__ bs)
{
    extern __shared__ char dsm[];
    const uint32_t smb = smem_u32(dsm);

    const int tid  = threadIdx.x;
    const int lane = tid & 31;
    const int wid  = tid >> 5;
    const int wm   = wid & 3;
    const int wn   = wid >> 2;
    const int nt = blockIdx.x;
    const int mt = blockIdx.y;
    const int z  = blockIdx.z;

    const int xsel = (z <= 2) ? 0 : (z == 3) ? 1 : 2;
    const __nv_bfloat16* Xh = g_xh + (size_t)xsel * (BB*SSQ*HD);
    const __nv_bfloat16* Xl = g_xl + (size_t)xsel * (BB*SSQ*HD);
    const __nv_bfloat16* Wh = g_wh + (size_t)z * (HD*HD);
    const __nv_bfloat16* Wl = g_wl + (size_t)z * (HD*HD);
    const float* bias = (z==0)?bq:(z==1)?bk:(z==2)?bv:(z==3)?bt:bs;

    float D[2][8][4];
#pragma unroll
    for (int mf = 0; mf < 2; mf++)
#pragma unroll
        for (int nf = 0; nf < 8; nf++)
#pragma unroll
            for (int c = 0; c < 4; c++) D[mf][nf][c] = 0.f;

    const int a_row = wm*32 + (lane & 15);
    const int a_hi  = (lane >> 4);
    const int b_row = wn*64 + (lane & 7) + (lane >> 4)*8;
    const int b_hi  = (lane >> 3) & 1;

    auto issue = [&](int buf, int kb) {
        const uint32_t so = smb + buf*PSTAGE;
#pragma unroll
        for (int l = 0; l < 4; l++) {
            const int flat = tid + l*256;
            const int r   = flat >> 3;
            const int seg = flat & 7;
            const uint32_t swo = SWZ128((uint32_t)(r*128 + seg*16));
            const size_t ga = (size_t)(mt*128 + r)*HD + kb*64 + seg*8;
            const size_t gb = (size_t)(nt*128 + r)*HD + kb*64 + seg*8;
            cp16(so +     0 + swo, Xh + ga);
            cp16(so + 16384 + swo, Xl + ga);
            cp16(so + 32768 + swo, Wh + gb);
            cp16(so + 49152 + swo, Wl + gb);
        }
    };

    issue(0, 0); CP_COMMIT();
    issue(1, 1); CP_COMMIT();

    for (int kb = 0; kb < 12; kb++) {
        if (kb < 11) { CP_WAIT(1); } else { CP_WAIT(0); }
        __syncthreads();
        if (kb + 2 < 12) { issue((kb + 2) % 3, kb + 2); CP_COMMIT(); }
        const uint32_t so = smb + (kb % 3)*PSTAGE;

#pragma unroll
        for (int ks = 0; ks < 4; ks++) {
            uint32_t ah[2][4], al[2][4];
#pragma unroll
            for (int mf = 0; mf < 2; mf++) {
                const uint32_t byo = SWZ128((uint32_t)((a_row + mf*16)*128 + (ks*2 + a_hi)*16));
                LDSM4(ah[mf], so +     0 + byo);
                LDSM4(al[mf], so + 16384 + byo);
            }
#pragma unroll
            for (int g = 0; g < 4; g++) {
                uint32_t bh4[4], bl4[4];
                const uint32_t byo = SWZ128((uint32_t)((b_row + g*16)*128 + (ks*2 + b_hi)*16));
                LDSM4(bh4, so + 32768 + byo);
                LDSM4(bl4, so + 49152 + byo);
#pragma unroll
                for (int sub = 0; sub < 2; sub++) {
                    const int nf = 2*g + sub;
#pragma unroll
                    for (int mf = 0; mf < 2; mf++) {
                        MMA_BF16(D[mf][nf], ah[mf], bh4[2*sub], bh4[2*sub+1]);
                        MMA_BF16(D[mf][nf], ah[mf], bl4[2*sub], bl4[2*sub+1]);
                        MMA_BF16(D[mf][nf], al[mf], bh4[2*sub], bh4[2*sub+1]);
                    }
                }
            }
        }
    }

    // ---- epilogue ----
    const int b_ = (mt*128) >> 10;
    const int h  = nt*2 + wn;
    const size_t bh = (size_t)b_*NHD + h;

#pragma unroll
    for (int nf = 0; nf < 8; nf++) {
        const int col = nt*128 + wn*64 + nf*8 + (lane & 3)*2;
        const float b0 = bias[col], b1 = bias[col + 1];
#pragma unroll
        for (int mf = 0; mf < 2; mf++) {
            D[mf][nf][0] += b0; D[mf][nf][1] += b1;
            D[mf][nf][2] += b0; D[mf][nf][3] += b1;
        }
    }

    if (z <= 1) {
        __half* gq = (z == 0) ? g_q16 : g_k16;
#pragma unroll
        for (int mf = 0; mf < 2; mf++)
#pragma unroll
            for (int half = 0; half < 2; half++) {
                const int s_ = (mt*128 + wm*32 + mf*16 + half*8 + (lane >> 2)) & 1023;
                const size_t base = (bh*SSQ + s_)*DHD + (lane & 3)*2;
#pragma unroll
                for (int nf = 0; nf < 8; nf++) {
                    __half2 hv = __floats2half2_rn(D[mf][nf][half*2], D[mf][nf][half*2+1]);
                    *(uint32_t*)(gq + base + nf*8) = *(uint32_t*)&hv;
                }
            }
        return;
    }

    if (z >= 3) {
        __half* gt = (z == 3) ? g_t16 : g_s16;
        float* invn = (z == 3) ? g_itn : g_isn;
#pragma unroll
        for (int mf = 0; mf < 2; mf++)
#pragma unroll
            for (int half = 0; half < 2; half++) {
                const int s_ = (mt*128 + wm*32 + mf*16 + half*8 + (lane >> 2)) & 1023;
                const size_t base = (bh*SSQ + s_)*DHD + (lane & 3)*2;
                float ss = 0.f;
#pragma unroll
                for (int nf = 0; nf < 8; nf++) {
                    const float v0 = D[mf][nf][half*2], v1 = D[mf][nf][half*2+1];
                    ss = fmaf(v0, v0, fmaf(v1, v1, ss));
                    __half2 hv = __floats2half2_rn(v0, v1);
                    *(uint32_t*)(gt + base + nf*8) = *(uint32_t*)&hv;
                }
                ss += __shfl_xor_sync(0xffffffffu, ss, 1);
                ss += __shfl_xor_sync(0xffffffffu, ss, 2);
                if ((lane & 3) == 0)
                    invn[bh*SSQ + s_] = 1.0f / (sqrtf(ss) + EPSF);
            }
        return;
    }

    // z == 2: V -> transposed fp16 [bh][dim][tok] via smem stage
    float* S = (float*)dsm;
#pragma unroll
    for (int mf = 0; mf < 2; mf++) {
        __syncthreads();
#pragma unroll
        for (int half = 0; half < 2; half++) {
            const int rl = wm*16 + half*8 + (lane >> 2);
            const int c  = wn*64 + (lane & 3)*2;
#pragma unroll
            for (int nf = 0; nf < 8; nf++) {
                S[(c + nf*8    )*66 + rl] = D[mf][nf][half*2];
                S[(c + nf*8 + 1)*66 + rl] = D[mf][nf][half*2+1];
            }
        }
        __syncthreads();
#pragma unroll
        for (int l = 0; l < 8; l++) {
            const int e  = tid + l*256;
            const int d  = e >> 4;
            const int r4 = (e & 15) * 4;
            float4 v = make_float4(S[d*66 + r4], S[d*66 + r4 + 1],
                                   S[d*66 + r4 + 2], S[d*66 + r4 + 3]);
            const int tk = (mt*128 + mf*16 + (r4 >> 4)*32 + (r4 & 15)) & 1023;
            const int hh = nt*2 + (d >> 6);
            const int dl = d & 63;
            const size_t ob = (((size_t)b_*NHD + hh)*DHD + dl)*SSQ + tk;
            __half2 hA = __floats2half2_rn(v.x, v.y);
            __half2 hB = __floats2half2_rn(v.z, v.w);
            uint2 hu = make_uint2(*(uint32_t*)&hA, *(uint32_t*)&hB);
            *(uint2*)(g_vT16 + ob) = hu;
        }
    }
}

// ---------------------------------------------------------------------------
// HMMA flash attention: 128 thr / 4 warps / 64 queries, 2 blocks per SM.
// 2x2 warp grid: warp = (qgrp = w>>1) x (kgrp = w&1); each warp does
// 32 queries x 32 keys per chunk -> B-side LDSM traffic halves (80->48/warp).
// Cross-warp softmax stats via 1KB smem comm; O partials combined at epilogue.
// smem = 16384(qt/qs) + 1024(comm) + 2*33024(stages) = 83456 -> 2 blocks/SM.
// ---------------------------------------------------------------------------
#define AQT       16384
#define COMM_OFF  16384                 // commM [128]f, commL [128]f
#define STG_OFF   17408
#define STAGE_SZ  33024                 // k16,t,s,v16 (4x8KB) + mask 256B
#define ATTN_SMEM (STG_OFF + 2*STAGE_SZ)  // 83456

__global__ __launch_bounds__(128, 2) void attn_hmma_kernel(const float* __restrict__ mask,
                                                           float* __restrict__ out)
{
    extern __shared__ char sbuf[];
    const uint32_t smb = smem_u32(sbuf);
    float* commM = (float*)(sbuf + COMM_OFF);
    float* commL = commM + 128;
    const int tid = threadIdx.x;
    const int lane = tid & 31;
    const int w = tid >> 5;
    const int qgrp = w >> 1;            // 0: rows 0-31, 1: rows 32-63
    const int kgrp = w & 1;             // 0: keys 0-31, 1: keys 32-63
    const int bh = blockIdx.y;
    const int b_ = bh / NHD;
    const int h  = bh - b_*NHD;
    const int qb = blockIdx.x * 64;

    const __half* q16p = g_q16 + (size_t)bh*SSQ*DHD;
    const __half* k16p = g_k16 + (size_t)bh*SSQ*DHD;
    const __half* qtp  = g_t16 + (size_t)bh*SSQ*DHD;
    const __half* qsp  = g_s16 + (size_t)bh*SSQ*DHD;
    const __half* vp   = g_vT16 + (size_t)bh*DHD*SSQ;
    const float* maskb = mask + (size_t)b_*SSQ;

    const int arow0 = qgrp*32 + (lane & 15);   // + mf*16
    const int asel  = lane >> 4;
    const int brow  = (lane & 7) + (lane >> 4)*8;
    const int bsel  = (lane >> 3) & 1;
    const int rowq  = lane >> 2;               // quad row 0..7
    const int rl0   = qgrp*32;                 // block-local row base for this warp

    // ---- prologue: qt/qs -> permanent smem; q16 staged then registered ----
#pragma unroll
    for (int l = 0; l < 4; l++) {
        const int flat = tid + l*128;
        const int r = flat >> 3, seg = flat & 7;
        const uint32_t swo = SWZ128((uint32_t)(r*128 + seg*16));
        const size_t src = (size_t)(qb + r)*DHD + seg*8;
        cp16(smb +    0 + swo, qtp + src);
        cp16(smb + 8192 + swo, qsp + src);
        cp16(smb + STG_OFF + swo, q16p + src);   // transient in stage 0
    }
    CP_COMMIT(); CP_WAIT(0);
    __syncthreads();

    uint32_t qf[2][4][4];   // [mf][ks]
#pragma unroll
    for (int mf = 0; mf < 2; mf++)
#pragma unroll
        for (int ks = 0; ks < 4; ks++) {
            const uint32_t aoff = SWZ128((uint32_t)((arow0 + mf*16)*128 + (ks*2 + asel)*16));
            LDSM4(qf[mf][ks], smb + STG_OFF + aoff);
        }
    __syncthreads();

    // ---- K/V stage issue ----
    auto issue = [&](int buf, int kb0) {
        const uint32_t so = smb + STG_OFF + buf*STAGE_SZ;
#pragma unroll
        for (int l = 0; l < 4; l++) {
            const int flat = tid + l*128;
            const int r = flat >> 3, seg = flat & 7;
            const uint32_t swo = SWZ128((uint32_t)(r*128 + seg*16));
            const size_t srcK = (size_t)(kb0 + r)*DHD + seg*8;
            cp16(so +     0 + swo, k16p + srcK);
            cp16(so +  8192 + swo, qtp + srcK);
            cp16(so + 16384 + swo, qsp + srcK);
            const size_t srcV = (size_t)r*SSQ + kb0 + seg*8;
            cp16(so + 24576 + swo, vp + srcV);
        }
        if (tid < 16) cp16(so + 32768 + tid*16, maskb + kb0 + tid*4);
    };

    issue(0, 0); CP_COMMIT();

    // rowscale * log2e for this thread's 4 rows: [mf][half]
    float rs[2][2];
#pragma unroll
    for (int mf = 0; mf < 2; mf++)
#pragma unroll
        for (int hf = 0; hf < 2; hf++) {
            const int q = qb + rl0 + mf*16 + hf*8 + rowq;
            rs[mf][hf] = g_itn[(size_t)bh*SSQ + q] * g_isn[(size_t)bh*SSQ + q] * (0.125f * LOG2E);
        }

    float O[2][8][4];
#pragma unroll
    for (int mf = 0; mf < 2; mf++)
#pragma unroll
        for (int nf = 0; nf < 8; nf++)
#pragma unroll
            for (int c = 0; c < 4; c++) O[mf][nf][c] = 0.f;
    float m_[2][2] = {{-1e30f,-1e30f},{-1e30f,-1e30f}};
    float l_[2][2] = {{0.f,0.f},{0.f,0.f}};

    for (int c = 0; c < 16; c++) {
        const int buf = c & 1;
        const uint32_t so = smb + STG_OFF + buf*STAGE_SZ;
        const char* sp = sbuf + STG_OFF + buf*STAGE_SZ;

        if (c + 1 < 16) { issue(buf ^ 1, (c + 1)*64); CP_COMMIT(); CP_WAIT(1); }
        else            { CP_WAIT(0); }
        __syncthreads();

        // ---- scores: this warp's 32 queries x its 32 keys ----
        float sb[2][4][4], st4[2][4][4], ss4[2][4][4];
#pragma unroll
        for (int mf = 0; mf < 2; mf++)
#pragma unroll
            for (int nf = 0; nf < 4; nf++)
#pragma unroll
                for (int cc = 0; cc < 4; cc++) {
                    sb[mf][nf][cc] = 0.f; st4[mf][nf][cc] = 0.f; ss4[mf][nf][cc] = 0.f;
                }

#pragma unroll
        for (int ks = 0; ks < 4; ks++) {
            uint32_t at_[2][4], as_[2][4];
#pragma unroll
            for (int mf = 0; mf < 2; mf++) {
                const uint32_t aoff = SWZ128((uint32_t)((arow0 + mf*16)*128 + (ks*2 + asel)*16));
                LDSM4(at_[mf], smb +    0 + aoff);
                LDSM4(as_[mf], smb + 8192 + aoff);
            }
#pragma unroll
            for (int g2 = 0; g2 < 2; g2++) {
                const int grow = kgrp*32 + g2*16 + brow;
                const uint32_t boff = SWZ128((uint32_t)(grow*128 + (ks*2 + bsel)*16));
                uint32_t k4[4], bt4[4], bs4[4];
                LDSM4(k4,  so +     0 + boff);
                LDSM4(bt4, so +  8192 + boff);
                LDSM4(bs4, so + 16384 + boff);
#pragma unroll
                for (int sub = 0; sub < 2; sub++) {
                    const int nf = 2*g2 + sub;
#pragma unroll
                    for (int mf = 0; mf < 2; mf++) {
                        MMA_F16(sb[mf][nf],  qf[mf][ks], k4[2*sub],  k4[2*sub+1]);
                        MMA_F16(st4[mf][nf], at_[mf],    bt4[2*sub], bt4[2*sub+1]);
                        MMA_F16(ss4[mf][nf], as_[mf],    bs4[2*sub], bs4[2*sub+1]);
                    }
                }
            }
        }

        // ---- logits + local row max ----
        const float* mkp = (const float*)(sp + 32768);
        float mloc[2][2] = {{-1e30f,-1e30f},{-1e30f,-1e30f}};
#pragma unroll
        for (int nf = 0; nf < 4; nf++) {
            const float2 mk = *(const float2*)(mkp + kgrp*32 + nf*8 + (lane & 3)*2);
            const float mk2x = mk.x * LOG2E, mk2y = mk.y * LOG2E;
#pragma unroll
            for (int mf = 0; mf < 2; mf++) {
                float s0 = fmaf(sb[mf][nf][0]*st4[mf][nf][0]*ss4[mf][nf][0], rs[mf][0], mk2x);
                float s1 = fmaf(sb[mf][nf][1]*st4[mf][nf][1]*ss4[mf][nf][1], rs[mf][0], mk2y);
                float s2 = fmaf(sb[mf][nf][2]*st4[mf][nf][2]*ss4[mf][nf][2], rs[mf][1], mk2x);
                float s3 = fmaf(sb[mf][nf][3]*st4[mf][nf][3]*ss4[mf][nf][3], rs[mf][1], mk2y);
                sb[mf][nf][0] = s0; sb[mf][nf][1] = s1; sb[mf][nf][2] = s2; sb[mf][nf][3] = s3;
                mloc[mf][0] = fmaxf(mloc[mf][0], fmaxf(s0, s1));
                mloc[mf][1] = fmaxf(mloc[mf][1], fmaxf(s2, s3));
            }
        }
#pragma unroll
        for (int mf = 0; mf < 2; mf++)
#pragma unroll
            for (int hf = 0; hf < 2; hf++) {
                mloc[mf][hf] = fmaxf(mloc[mf][hf], __shfl_xor_sync(0xffffffffu, mloc[mf][hf], 1));
                mloc[mf][hf] = fmaxf(mloc[mf][hf], __shfl_xor_sync(0xffffffffu, mloc[mf][hf], 2));
            }

        // ---- exchange max with key-partner warp (w^1) ----
        if ((lane & 3) == 0) {
#pragma unroll
            for (int mf = 0; mf < 2; mf++)
#pragma unroll
                for (int hf = 0; hf < 2; hf++)
                    commM[w*32 + mf*16 + hf*8 + rowq] = mloc[mf][hf];
        }
        __syncthreads();

        float cr[2][2];
        bool allsame = true;
#pragma unroll
        for (int mf = 0; mf < 2; mf++)
#pragma unroll
            for (int hf = 0; hf < 2; hf++) {
                const float pm = commM[(w^1)*32 + mf*16 + hf*8 + rowq];
                const float mn = fmaxf(m_[mf][hf], fmaxf(mloc[mf][hf], pm));
                cr[mf][hf] = ex2f(m_[mf][hf] - mn);
                allsame &= (mn == m_[mf][hf]);
                m_[mf][hf] = mn;
            }
        const unsigned same = __all_sync(0xffffffffu, allsame);

        // ---- exp + local row sums ----
        float rsum[2][2] = {{0.f,0.f},{0.f,0.f}};
#pragma unroll
        for (int mf = 0; mf < 2; mf++)
#pragma unroll
            for (int nf = 0; nf < 4; nf++) {
                float p0 = ex2f(sb[mf][nf][0] - m_[mf][0]);
                float p1 = ex2f(sb[mf][nf][1] - m_[mf][0]);
                float p2 = ex2f(sb[mf][nf][2] - m_[mf][1]);
                float p3 = ex2f(sb[mf][nf][3] - m_[mf][1]);
                sb[mf][nf][0] = p0; sb[mf][nf][1] = p1; sb[mf][nf][2] = p2; sb[mf][nf][3] = p3;
                rsum[mf][0] += p0 + p1;
                rsum[mf][1] += p2 + p3;
            }
        if (!same) {
#pragma unroll
            for (int mf = 0; mf < 2; mf++)
#pragma unroll
                for (int nf = 0; nf < 8; nf++) {
                    O[mf][nf][0] *= cr[mf][0]; O[mf][nf][1] *= cr[mf][0];
                    O[mf][nf][2] *= cr[mf][1]; O[mf][nf][3] *= cr[mf][1];
                }
        }
#pragma unroll
        for (int mf = 0; mf < 2; mf++)
#pragma unroll
            for (int hf = 0; hf < 2; hf++) {
                rsum[mf][hf] += __shfl_xor_sync(0xffffffffu, rsum[mf][hf], 1);
                rsum[mf][hf] += __shfl_xor_sync(0xffffffffu, rsum[mf][hf], 2);
            }
        if ((lane & 3) == 0) {
#pragma unroll
            for (int mf = 0; mf < 2; mf++)
#pragma unroll
                for (int hf = 0; hf < 2; hf++)
                    commL[w*32 + mf*16 + hf*8 + rowq] = rsum[mf][hf];
        }
        __syncthreads();
#pragma unroll
        for (int mf = 0; mf < 2; mf++)
#pragma unroll
            for (int hf = 0; hf < 2; hf++) {
                const float pr = commL[(w^1)*32 + mf*16 + hf*8 + rowq];
                l_[mf][hf] = l_[mf][hf]*cr[mf][hf] + rsum[mf][hf] + pr;
            }

        // ---- P @ V over this warp's 32 keys ----
#pragma unroll
        for (int j = 0; j < 2; j++) {          // 16-key group within warp's keys
            uint32_t pf[2][4];
#pragma unroll
            for (int mf = 0; mf < 2; mf++)
#pragma unroll
                for (int half = 0; half < 2; half++) {
                    const int nf = 2*j + half;
#pragma unroll
                    for (int rr = 0; rr < 2; rr++) {
                        __half2 hv = __floats2half2_rn(sb[mf][nf][rr*2], sb[mf][nf][rr*2+1]);
                        pf[mf][half*2 + rr] = *(uint32_t*)&hv;
                    }
                }
            const int kg = kgrp*2 + j;         // global 16-key group in chunk
#pragma unroll
            for (int g = 0; g < 4; g++) {
                const uint32_t boff = SWZ128((uint32_t)((g*16 + brow)*128 + (kg*2 + bsel)*16));
                uint32_t v4[4];
                LDSM4(v4, so + 24576 + boff);
#pragma unroll
                for (int sub = 0; sub < 2; sub++)
#pragma unroll
                    for (int mf = 0; mf < 2; mf++)
                        MMA_F16(O[mf][2*g + sub], pf[mf], v4[2*sub], v4[2*sub+1]);
            }
        }
    }

    // ---- epilogue: combine O partials across key-partner warps ----
    float* Ocomb = (float*)(sbuf + STG_OFF);   // 64 x 66 floats = 16.9 KB
    __syncthreads();
    if (kgrp == 1) {
#pragma unroll
        for (int mf = 0; mf < 2; mf++)
#pragma unroll
            for (int hf = 0; hf < 2; hf++) {
                const int row = rl0 + mf*16 + hf*8 + rowq;
#pragma unroll
                for (int nf = 0; nf < 8; nf++) {
                    *(float2*)&Ocomb[row*66 + nf*8 + (lane & 3)*2] =
                        make_float2(O[mf][nf][hf*2], O[mf][nf][hf*2+1]);
                }
            }
    }
    __syncthreads();
    if (kgrp == 0) {
#pragma unroll
        for (int mf = 0; mf < 2; mf++)
#pragma unroll
            for (int hf = 0; hf < 2; hf++) {
                const int row = rl0 + mf*16 + hf*8 + rowq;
                const float il = 1.0f / l_[mf][hf];
                float* op = out + ((size_t)b_*SSQ + qb + row)*HD + h*DHD + (lane & 3)*2;
#pragma unroll
                for (int nf = 0; nf < 8; nf++) {
                    const float2 pv = *(const float2*)&Ocomb[row*66 + nf*8 + (lane & 3)*2];
                    *(float2*)(op + nf*8) = make_float2(
                        (O[mf][nf][hf*2]   + pv.x) * il,
                        (O[mf][nf][hf*2+1] + pv.y) * il);
                }
            }
    }
}

// ---------------------------------------------------------------------------
extern "C" void kernel_launch(void* const* d_in, const int* in_sizes, int n_in,
                              void* d_out, int out_size)
{
    const float* hs   = (const float*)d_in[0];
    const float* te   = (const float*)d_in[1];
    const float* se   = (const float*)d_in[2];
    const float* mask = (const float*)d_in[3];
    const float* Wq = (const float*)d_in[4];  const float* bq = (const float*)d_in[5];
    const float* Wk = (const float*)d_in[6];  const float* bk = (const float*)d_in[7];
    const float* Wv = (const float*)d_in[8];  const float* bv = (const float*)d_in[9];
    const float* Wt = (const float*)d_in[10]; const float* bt = (const float*)d_in[11];
    const float* Ws = (const float*)d_in[12]; const float* bs = (const float*)d_in[13];
    float* out = (float*)d_out;

    dim3 gx((BB*SSQ*HD)/4/256, 3);
    split_x_kernel<<<gx, 256>>>(hs, te, se);
    dim3 gw((HD*HD)/4/256, 5);
    split_w_kernel<<<gw, 256>>>(Wq, Wk, Wv, Wt, Ws);

    cudaFuncSetAttribute(proj_hmma_kernel, cudaFuncAttributeMaxDynamicSharedMemorySize, PROJ_SMEM);
    dim3 gp(HD/128, (BB*SSQ)/128, 5);   // (6, 32, 5)
    proj_hmma_kernel<<<gp, 256, PROJ_SMEM>>>(bq, bk, bv, bt, bs);

    cudaFuncSetAttribute(attn_hmma_kernel, cudaFuncAttributeMaxDynamicSharedMemorySize, ATTN_SMEM);
    dim3 ga(SSQ/64, BB*NHD);            // (16, 48)
    attn_hmma_kernel<<<ga, 128, ATTN_SMEM>>>(mask, out);
}

// round 17
// speedup vs baseline: 1.0342x; 1.0342x over previous
#include <cuda_runtime.h>
#include <cuda_bf16.h>
#include <cuda_fp16.h>
#include <math.h>
#include <stdint.h>

#define HD   768
#define NHD  12
#define DHD  64
#define BB   4
#define SSQ  1024
#define EPSF 1e-6f
#define LOG2E 1.4426950408889634f

#define SWZ128(x) ((x) ^ (((x) >> 3) & 0x70))

__device__ __forceinline__ uint32_t smem_u32(const void* p) {
    uint32_t a;
    asm("{ .reg .u64 t; cvta.to.shared.u64 t, %1; cvt.u32.u64 %0, t; }" : "=r"(a) : "l"(p));
    return a;
}
__device__ __forceinline__ float ex2f(float x) {
    float r; asm("ex2.approx.f32 %0, %1;" : "=f"(r) : "f"(x)); return r;
}

#define LDSM4(r, addr) \
    asm volatile("ldmatrix.sync.aligned.m8n8.x4.shared.b16 {%0,%1,%2,%3}, [%4];" \
        : "=r"((r)[0]), "=r"((r)[1]), "=r"((r)[2]), "=r"((r)[3]) : "r"(addr))

#define MMA_BF16(d, a, b0, b1) \
    asm volatile("mma.sync.aligned.m16n8k16.row.col.f32.bf16.bf16.f32 " \
        "{%0,%1,%2,%3}, {%4,%5,%6,%7}, {%8,%9}, {%0,%1,%2,%3};" \
        : "+f"((d)[0]), "+f"((d)[1]), "+f"((d)[2]), "+f"((d)[3]) \
        : "r"((a)[0]), "r"((a)[1]), "r"((a)[2]), "r"((a)[3]), "r"(b0), "r"(b1))

#define MMA_F16(d, a, b0, b1) \
    asm volatile("mma.sync.aligned.m16n8k16.row.col.f32.f16.f16.f32 " \
        "{%0,%1,%2,%3}, {%4,%5,%6,%7}, {%8,%9}, {%0,%1,%2,%3};" \
        : "+f"((d)[0]), "+f"((d)[1]), "+f"((d)[2]), "+f"((d)[3]) \
        : "r"((a)[0]), "r"((a)[1]), "r"((a)[2]), "r"((a)[3]), "r"(b0), "r"(b1))

__device__ __forceinline__ void cp16(uint32_t d, const void* s) {
    asm volatile("cp.async.cg.shared.global [%0], [%1], 16;" :: "r"(d), "l"(s) : "memory");
}
#define CP_COMMIT() asm volatile("cp.async.commit_group;" ::: "memory")
#define CP_WAIT(n)  asm volatile("cp.async.wait_group %0;" :: "n"(n) : "memory")

// ---------------------------------------------------------------------------
// Scratch (allocation-free rule: __device__ globals)
// ---------------------------------------------------------------------------
__device__ __half g_q16[BB*NHD*SSQ*DHD];   // q fp16 [bh][tok][dim]
__device__ __half g_k16[BB*NHD*SSQ*DHD];
__device__ __half g_t16[BB*NHD*SSQ*DHD];
__device__ __half g_s16[BB*NHD*SSQ*DHD];
__device__ __half g_vT16[BB*NHD*DHD*SSQ];  // V fp16 [bh][dim][tok]
__device__ float g_itn[BB*NHD*SSQ];
__device__ float g_isn[BB*NHD*SSQ];

// bf16 split-precision GEMM inputs
__device__ __nv_bfloat16 g_xh[3*BB*SSQ*HD];
__device__ __nv_bfloat16 g_xl[3*BB*SSQ*HD];
__device__ __nv_bfloat16 g_wh[5*HD*HD];
__device__ __nv_bfloat16 g_wl[5*HD*HD];

// ---------------------------------------------------------------------------
// fp32 -> bf16 hi/lo split kernels
// ---------------------------------------------------------------------------
__global__ __launch_bounds__(256) void split_x_kernel(
    const float* __restrict__ hs, const float* __restrict__ te, const float* __restrict__ se)
{
    const float* src = (blockIdx.y == 0) ? hs : (blockIdx.y == 1) ? te : se;
    const size_t off = (size_t)blockIdx.y * (size_t)(BB*SSQ*HD);
    size_t i = ((size_t)blockIdx.x * blockDim.x + threadIdx.x) * 4;
    if (i >= (size_t)(BB*SSQ*HD)) return;
    float4 x = *(const float4*)(src + i);
    __nv_bfloat16 h0 = __float2bfloat16(x.x), h1 = __float2bfloat16(x.y);
    __nv_bfloat16 h2 = __float2bfloat16(x.z), h3 = __float2bfloat16(x.w);
    __nv_bfloat162 hA; hA.x = h0; hA.y = h1;
    __nv_bfloat162 hB; hB.x = h2; hB.y = h3;
    __nv_bfloat162 lA; lA.x = __float2bfloat16(x.x - __bfloat162float(h0));
                       lA.y = __float2bfloat16(x.y - __bfloat162float(h1));
    __nv_bfloat162 lB; lB.x = __float2bfloat16(x.z - __bfloat162float(h2));
                       lB.y = __float2bfloat16(x.w - __bfloat162float(h3));
    *(__nv_bfloat162*)(g_xh + off + i)     = hA;
    *(__nv_bfloat162*)(g_xh + off + i + 2) = hB;
    *(__nv_bfloat162*)(g_xl + off + i)     = lA;
    *(__nv_bfloat162*)(g_xl + off + i + 2) = lB;
}

__global__ __launch_bounds__(256) void split_w_kernel(
    const float* __restrict__ Wq, const float* __restrict__ Wk, const float* __restrict__ Wv,
    const float* __restrict__ Wt, const float* __restrict__ Ws)
{
    const int z = blockIdx.y;
    const float* src = (z==0)?Wq:(z==1)?Wk:(z==2)?Wv:(z==3)?Wt:Ws;
    const size_t off = (size_t)z * (size_t)(HD*HD);
    size_t i = ((size_t)blockIdx.x * blockDim.x + threadIdx.x) * 4;
    if (i >= (size_t)(HD*HD)) return;
    float4 x = *(const float4*)(src + i);
    __nv_bfloat16 h0 = __float2bfloat16(x.x), h1 = __float2bfloat16(x.y);
    __nv_bfloat16 h2 = __float2bfloat16(x.z), h3 = __float2bfloat16(x.w);
    __nv_bfloat162 hA; hA.x = h0; hA.y = h1;
    __nv_bfloat162 hB; hB.x = h2; hB.y = h3;
    __nv_bfloat162 lA; lA.x = __float2bfloat16(x.x - __bfloat162float(h0));
                       lA.y = __float2bfloat16(x.y - __bfloat162float(h1));
    __nv_bfloat162 lB; lB.x = __float2bfloat16(x.z - __bfloat162float(h2));
                       lB.y = __float2bfloat16(x.w - __bfloat162float(h3));
    *(__nv_bfloat162*)(g_wh + off + i)     = hA;
    *(__nv_bfloat162*)(g_wh + off + i + 2) = hB;
    *(__nv_bfloat162*)(g_wl + off + i)     = lA;
    *(__nv_bfloat162*)(g_wl + off + i + 2) = lB;
}

// ---------------------------------------------------------------------------
// HMMA projection GEMM (split hh+hl+lh), cp.async 3-stage pipeline.  (unchanged)
// ---------------------------------------------------------------------------
#define PSTAGE     65536
#define PROJ_SMEM  (3*PSTAGE)

__global__ __launch_bounds__(256) void proj_hmma_kernel(
    const float* __restrict__ bq, const float* __restrict__ bk,
    const float* __restrict__ bv, const float* __restrict__ bt,
    const float* __restrict__ bs)
{
    extern __shared__ char dsm[];
    const uint32_t smb = smem_u32(dsm);

    const int tid  = threadIdx.x;
    const int lane = tid & 31;
    const int wid  = tid >> 5;
    const int wm   = wid & 3;
    const int wn   = wid >> 2;
    const int nt = blockIdx.x;
    const int mt = blockIdx.y;
    const int z  = blockIdx.z;

    const int xsel = (z <= 2) ? 0 : (z == 3) ? 1 : 2;
    const __nv_bfloat16* Xh = g_xh + (size_t)xsel * (BB*SSQ*HD);
    const __nv_bfloat16* Xl = g_xl + (size_t)xsel * (BB*SSQ*HD);
    const __nv_bfloat16* Wh = g_wh + (size_t)z * (HD*HD);
    const __nv_bfloat16* Wl = g_wl + (size_t)z * (HD*HD);
    const float* bias = (z==0)?bq:(z==1)?bk:(z==2)?bv:(z==3)?bt:bs;

    float D[2][8][4];
#pragma unroll
    for (int mf = 0; mf < 2; mf++)
#pragma unroll
        for (int nf = 0; nf < 8; nf++)
#pragma unroll
            for (int c = 0; c < 4; c++) D[mf][nf][c] = 0.f;

    const int a_row = wm*32 + (lane & 15);
    const int a_hi  = (lane >> 4);
    const int b_row = wn*64 + (lane & 7) + (lane >> 4)*8;
    const int b_hi  = (lane >> 3) & 1;

    auto issue = [&](int buf, int kb) {
        const uint32_t so = smb + buf*PSTAGE;
#pragma unroll
        for (int l = 0; l < 4; l++) {
            const int flat = tid + l*256;
            const int r   = flat >> 3;
            const int seg = flat & 7;
            const uint32_t swo = SWZ128((uint32_t)(r*128 + seg*16));
            const size_t ga = (size_t)(mt*128 + r)*HD + kb*64 + seg*8;
            const size_t gb = (size_t)(nt*128 + r)*HD + kb*64 + seg*8;
            cp16(so +     0 + swo, Xh + ga);
            cp16(so + 16384 + swo, Xl + ga);
            cp16(so + 32768 + swo, Wh + gb);
            cp16(so + 49152 + swo, Wl + gb);
        }
    };

    issue(0, 0); CP_COMMIT();
    issue(1, 1); CP_COMMIT();

    for (int kb = 0; kb < 12; kb++) {
        if (kb < 11) { CP_WAIT(1); } else { CP_WAIT(0); }
        __syncthreads();
        if (kb + 2 < 12) { issue((kb + 2) % 3, kb + 2); CP_COMMIT(); }
        const uint32_t so = smb + (kb % 3)*PSTAGE;

#pragma unroll
        for (int ks = 0; ks < 4; ks++) {
            uint32_t ah[2][4], al[2][4];
#pragma unroll
            for (int mf = 0; mf < 2; mf++) {
                const uint32_t byo = SWZ128((uint32_t)((a_row + mf*16)*128 + (ks*2 + a_hi)*16));
                LDSM4(ah[mf], so +     0 + byo);
                LDSM4(al[mf], so + 16384 + byo);
            }
#pragma unroll
            for (int g = 0; g < 4; g++) {
                uint32_t bh4[4], bl4[4];
                const uint32_t byo = SWZ128((uint32_t)((b_row + g*16)*128 + (ks*2 + b_hi)*16));
                LDSM4(bh4, so + 32768 + byo);
                LDSM4(bl4, so + 49152 + byo);
#pragma unroll
                for (int sub = 0; sub < 2; sub++) {
                    const int nf = 2*g + sub;
#pragma unroll
                    for (int mf = 0; mf < 2; mf++) {
                        MMA_BF16(D[mf][nf], ah[mf], bh4[2*sub], bh4[2*sub+1]);
                        MMA_BF16(D[mf][nf], ah[mf], bl4[2*sub], bl4[2*sub+1]);
                        MMA_BF16(D[mf][nf], al[mf], bh4[2*sub], bh4[2*sub+1]);
                    }
                }
            }
        }
    }

    // ---- epilogue ----
    const int b_ = (mt*128) >> 10;
    const int h  = nt*2 + wn;
    const size_t bh = (size_t)b_*NHD + h;

#pragma unroll
    for (int nf = 0; nf < 8; nf++) {
        const int col = nt*128 + wn*64 + nf*8 + (lane & 3)*2;
        const float b0 = bias[col], b1 = bias[col + 1];
#pragma unroll
        for (int mf = 0; mf < 2; mf++) {
            D[mf][nf][0] += b0; D[mf][nf][1] += b1;
            D[mf][nf][2] += b0; D[mf][nf][3] += b1;
        }
    }

    if (z <= 1) {
        __half* gq = (z == 0) ? g_q16 : g_k16;
#pragma unroll
        for (int mf = 0; mf < 2; mf++)
#pragma unroll
            for (int half = 0; half < 2; half++) {
                const int s_ = (mt*128 + wm*32 + mf*16 + half*8 + (lane >> 2)) & 1023;
                const size_t base = (bh*SSQ + s_)*DHD + (lane & 3)*2;
#pragma unroll
                for (int nf = 0; nf < 8; nf++) {
                    __half2 hv = __floats2half2_rn(D[mf][nf][half*2], D[mf][nf][half*2+1]);
                    *(uint32_t*)(gq + base + nf*8) = *(uint32_t*)&hv;
                }
            }
        return;
    }

    if (z >= 3) {
        __half* gt = (z == 3) ? g_t16 : g_s16;
        float* invn = (z == 3) ? g_itn : g_isn;
#pragma unroll
        for (int mf = 0; mf < 2; mf++)
#pragma unroll
            for (int half = 0; half < 2; half++) {
                const int s_ = (mt*128 + wm*32 + mf*16 + half*8 + (lane >> 2)) & 1023;
                const size_t base = (bh*SSQ + s_)*DHD + (lane & 3)*2;
                float ss = 0.f;
#pragma unroll
                for (int nf = 0; nf < 8; nf++) {
                    const float v0 = D[mf][nf][half*2], v1 = D[mf][nf][half*2+1];
                    ss = fmaf(v0, v0, fmaf(v1, v1, ss));
                    __half2 hv = __floats2half2_rn(v0, v1);
                    *(uint32_t*)(gt + base + nf*8) = *(uint32_t*)&hv;
                }
                ss += __shfl_xor_sync(0xffffffffu, ss, 1);
                ss += __shfl_xor_sync(0xffffffffu, ss, 2);
                if ((lane & 3) == 0)
                    invn[bh*SSQ + s_] = 1.0f / (sqrtf(ss) + EPSF);
            }
        return;
    }

    // z == 2: V -> transposed fp16 [bh][dim][tok] via smem stage
    float* S = (float*)dsm;
#pragma unroll
    for (int mf = 0; mf < 2; mf++) {
        __syncthreads();
#pragma unroll
        for (int half = 0; half < 2; half++) {
            const int rl = wm*16 + half*8 + (lane >> 2);
            const int c  = wn*64 + (lane & 3)*2;
#pragma unroll
            for (int nf = 0; nf < 8; nf++) {
                S[(c + nf*8    )*66 + rl] = D[mf][nf][half*2];
                S[(c + nf*8 + 1)*66 + rl] = D[mf][nf][half*2+1];
            }
        }
        __syncthreads();
#pragma unroll
        for (int l = 0; l < 8; l++) {
            const int e  = tid + l*256;
            const int d  = e >> 4;
            const int r4 = (e & 15) * 4;
            float4 v = make_float4(S[d*66 + r4], S[d*66 + r4 + 1],
                                   S[d*66 + r4 + 2], S[d*66 + r4 + 3]);
            const int tk = (mt*128 + mf*16 + (r4 >> 4)*32 + (r4 & 15)) & 1023;
            const int hh = nt*2 + (d >> 6);
            const int dl = d & 63;
            const size_t ob = (((size_t)b_*NHD + hh)*DHD + dl)*SSQ + tk;
            __half2 hA = __floats2half2_rn(v.x, v.y);
            __half2 hB = __floats2half2_rn(v.z, v.w);
            uint2 hu = make_uint2(*(uint32_t*)&hA, *(uint32_t*)&hB);
            *(uint2*)(g_vT16 + ob) = hu;
        }
    }
}

// ---------------------------------------------------------------------------
// HMMA flash attention: 128 thr / 4 warps / 128 queries, 2 blocks per SM.
// Each warp owns 32 query rows x ALL 64 keys (no cross-warp softmax).
// Keys processed in two 32-key units sequentially (score regs live per-unit).
// B-side LDSM amortized over 2x rows: 96 LDSM4 per warp-chunk for 2x work.
// smem = 32768(qt/qs) + 2*33024(stages) = 98816 -> 2 blocks/SM.
// ---------------------------------------------------------------------------
#define AQT       32768                 // qt (16KB) + qs (16KB), 128 rows
#define STG_OFF   32768
#define STAGE_SZ  33024                 // k16,t,s,v16 (4x8KB) + mask 256B
#define ATTN_SMEM (STG_OFF + 2*STAGE_SZ)  // 98816

__global__ __launch_bounds__(128, 2) void attn_hmma_kernel(const float* __restrict__ mask,
                                                           float* __restrict__ out)
{
    extern __shared__ char sbuf[];
    const uint32_t smb = smem_u32(sbuf);
    const int tid = threadIdx.x;
    const int lane = tid & 31;
    const int w = tid >> 5;             // warp owns rows w*32..w*32+31
    const int bh = blockIdx.y;
    const int b_ = bh / NHD;
    const int h  = bh - b_*NHD;
    const int qb = blockIdx.x * 128;

    const __half* q16p = g_q16 + (size_t)bh*SSQ*DHD;
    const __half* k16p = g_k16 + (size_t)bh*SSQ*DHD;
    const __half* qtp  = g_t16 + (size_t)bh*SSQ*DHD;
    const __half* qsp  = g_s16 + (size_t)bh*SSQ*DHD;
    const __half* vp   = g_vT16 + (size_t)bh*DHD*SSQ;
    const float* maskb = mask + (size_t)b_*SSQ;

    const int arow0 = w*32 + (lane & 15);   // + mf*16
    const int asel  = lane >> 4;
    const int brow  = (lane & 7) + (lane >> 4)*8;
    const int bsel  = (lane >> 3) & 1;
    const int rowq  = lane >> 2;

    // ---- prologue: qt/qs (128 rows) -> permanent smem; q16 staged ----
#pragma unroll
    for (int l = 0; l < 8; l++) {
        const int flat = tid + l*128;       // 0..1023
        const int r = flat >> 3, seg = flat & 7;
        const uint32_t swo = SWZ128((uint32_t)(r*128 + seg*16));
        const size_t src = (size_t)(qb + r)*DHD + seg*8;
        cp16(smb +     0 + swo, qtp + src);
        cp16(smb + 16384 + swo, qsp + src);
        cp16(smb + STG_OFF + swo, q16p + src);   // transient in stage 0
    }
    CP_COMMIT(); CP_WAIT(0);
    __syncthreads();

    uint32_t qf[2][4][4];   // [mf][ks]
#pragma unroll
    for (int mf = 0; mf < 2; mf++)
#pragma unroll
        for (int ks = 0; ks < 4; ks++) {
            const uint32_t aoff = SWZ128((uint32_t)((arow0 + mf*16)*128 + (ks*2 + asel)*16));
            LDSM4(qf[mf][ks], smb + STG_OFF + aoff);
        }
    __syncthreads();

    // ---- K/V stage issue ----
    auto issue = [&](int buf, int kb0) {
        const uint32_t so = smb + STG_OFF + buf*STAGE_SZ;
#pragma unroll
        for (int l = 0; l < 4; l++) {
            const int flat = tid + l*128;
            const int r = flat >> 3, seg = flat & 7;
            const uint32_t swo = SWZ128((uint32_t)(r*128 + seg*16));
            const size_t srcK = (size_t)(kb0 + r)*DHD + seg*8;
            cp16(so +     0 + swo, k16p + srcK);
            cp16(so +  8192 + swo, qtp + srcK);
            cp16(so + 16384 + swo, qsp + srcK);
            const size_t srcV = (size_t)r*SSQ + kb0 + seg*8;
            cp16(so + 24576 + swo, vp + srcV);
        }
        if (tid < 16) cp16(so + 32768 + tid*16, maskb + kb0 + tid*4);
    };

    issue(0, 0); CP_COMMIT();

    // rowscale * log2e: [mf][half]
    float rs[2][2];
#pragma unroll
    for (int mf = 0; mf < 2; mf++)
#pragma unroll
        for (int hf = 0; hf < 2; hf++) {
            const int q = qb + w*32 + mf*16 + hf*8 + rowq;
            rs[mf][hf] = g_itn[(size_t)bh*SSQ + q] * g_isn[(size_t)bh*SSQ + q] * (0.125f * LOG2E);
        }

    float O[2][8][4];
#pragma unroll
    for (int mf = 0; mf < 2; mf++)
#pragma unroll
        for (int nf = 0; nf < 8; nf++)
#pragma unroll
            for (int c = 0; c < 4; c++) O[mf][nf][c] = 0.f;
    float m_[2][2] = {{-1e30f,-1e30f},{-1e30f,-1e30f}};
    float l_[2][2] = {{0.f,0.f},{0.f,0.f}};

    for (int c = 0; c < 16; c++) {
        const int buf = c & 1;
        const uint32_t so = smb + STG_OFF + buf*STAGE_SZ;
        const char* sp = sbuf + STG_OFF + buf*STAGE_SZ;

        if (c + 1 < 16) { issue(buf ^ 1, (c + 1)*64); CP_COMMIT(); CP_WAIT(1); }
        else            { CP_WAIT(0); }
        __syncthreads();

        const float* mkp = (const float*)(sp + 32768);

#pragma unroll
        for (int u = 0; u < 2; u++) {       // two 32-key units
            // ---- scores: 32 rows x 32 keys ----
            float sb[2][4][4], st4[2][4][4], ss4[2][4][4];
#pragma unroll
            for (int mf = 0; mf < 2; mf++)
#pragma unroll
                for (int nf = 0; nf < 4; nf++)
#pragma unroll
                    for (int cc = 0; cc < 4; cc++) {
                        sb[mf][nf][cc] = 0.f; st4[mf][nf][cc] = 0.f; ss4[mf][nf][cc] = 0.f;
                    }

#pragma unroll
            for (int ks = 0; ks < 4; ks++) {
                uint32_t at_[2][4], as_[2][4];
#pragma unroll
                for (int mf = 0; mf < 2; mf++) {
                    const uint32_t aoff = SWZ128((uint32_t)((arow0 + mf*16)*128 + (ks*2 + asel)*16));
                    LDSM4(at_[mf], smb +     0 + aoff);
                    LDSM4(as_[mf], smb + 16384 + aoff);
                }
#pragma unroll
                for (int g2 = 0; g2 < 2; g2++) {
                    const int grow = u*32 + g2*16 + brow;
                    const uint32_t boff = SWZ128((uint32_t)(grow*128 + (ks*2 + bsel)*16));
                    uint32_t k4[4], bt4[4], bs4[4];
                    LDSM4(k4,  so +     0 + boff);
                    LDSM4(bt4, so +  8192 + boff);
                    LDSM4(bs4, so + 16384 + boff);
#pragma unroll
                    for (int sub = 0; sub < 2; sub++) {
                        const int nf = 2*g2 + sub;
#pragma unroll
                        for (int mf = 0; mf < 2; mf++) {
                            MMA_F16(sb[mf][nf],  qf[mf][ks], k4[2*sub],  k4[2*sub+1]);
                            MMA_F16(st4[mf][nf], at_[mf],    bt4[2*sub], bt4[2*sub+1]);
                            MMA_F16(ss4[mf][nf], as_[mf],    bs4[2*sub], bs4[2*sub+1]);
                        }
                    }
                }
            }

            // ---- logits + online softmax (warp-local, quad reduce) ----
            float mloc[2][2] = {{-1e30f,-1e30f},{-1e30f,-1e30f}};
#pragma unroll
            for (int nf = 0; nf < 4; nf++) {
                const float2 mk = *(const float2*)(mkp + u*32 + nf*8 + (lane & 3)*2);
                const float mk2x = mk.x * LOG2E, mk2y = mk.y * LOG2E;
#pragma unroll
                for (int mf = 0; mf < 2; mf++) {
                    float s0 = fmaf(sb[mf][nf][0]*st4[mf][nf][0]*ss4[mf][nf][0], rs[mf][0], mk2x);
                    float s1 = fmaf(sb[mf][nf][1]*st4[mf][nf][1]*ss4[mf][nf][1], rs[mf][0], mk2y);
                    float s2 = fmaf(sb[mf][nf][2]*st4[mf][nf][2]*ss4[mf][nf][2], rs[mf][1], mk2x);
                    float s3 = fmaf(sb[mf][nf][3]*st4[mf][nf][3]*ss4[mf][nf][3], rs[mf][1], mk2y);
                    sb[mf][nf][0] = s0; sb[mf][nf][1] = s1; sb[mf][nf][2] = s2; sb[mf][nf][3] = s3;
                    mloc[mf][0] = fmaxf(mloc[mf][0], fmaxf(s0, s1));
                    mloc[mf][1] = fmaxf(mloc[mf][1], fmaxf(s2, s3));
                }
            }
            float cr[2][2];
            bool allsame = true;
#pragma unroll
            for (int mf = 0; mf < 2; mf++)
#pragma unroll
                for (int hf = 0; hf < 2; hf++) {
                    mloc[mf][hf] = fmaxf(mloc[mf][hf], __shfl_xor_sync(0xffffffffu, mloc[mf][hf], 1));
                    mloc[mf][hf] = fmaxf(mloc[mf][hf], __shfl_xor_sync(0xffffffffu, mloc[mf][hf], 2));
                    const float mn = fmaxf(m_[mf][hf], mloc[mf][hf]);
                    cr[mf][hf] = ex2f(m_[mf][hf] - mn);
                    allsame &= (mn == m_[mf][hf]);
                    m_[mf][hf] = mn;
                }
            const unsigned same = __all_sync(0xffffffffu, allsame);

            float rsum[2][2] = {{0.f,0.f},{0.f,0.f}};
#pragma unroll
            for (int mf = 0; mf < 2; mf++)
#pragma unroll
                for (int nf = 0; nf < 4; nf++) {
                    float p0 = ex2f(sb[mf][nf][0] - m_[mf][0]);
                    float p1 = ex2f(sb[mf][nf][1] - m_[mf][0]);
                    float p2 = ex2f(sb[mf][nf][2] - m_[mf][1]);
                    float p3 = ex2f(sb[mf][nf][3] - m_[mf][1]);
                    sb[mf][nf][0] = p0; sb[mf][nf][1] = p1; sb[mf][nf][2] = p2; sb[mf][nf][3] = p3;
                    rsum[mf][0] += p0 + p1;
                    rsum[mf][1] += p2 + p3;
                }
            if (!same) {
#pragma unroll
                for (int mf = 0; mf < 2; mf++)
#pragma unroll
                    for (int nf = 0; nf < 8; nf++) {
                        O[mf][nf][0] *= cr[mf][0]; O[mf][nf][1] *= cr[mf][0];
                        O[mf][nf][2] *= cr[mf][1]; O[mf][nf][3] *= cr[mf][1];
                    }
            }
#pragma unroll
            for (int mf = 0; mf < 2; mf++)
#pragma unroll
                for (int hf = 0; hf < 2; hf++) {
                    rsum[mf][hf] += __shfl_xor_sync(0xffffffffu, rsum[mf][hf], 1);
                    rsum[mf][hf] += __shfl_xor_sync(0xffffffffu, rsum[mf][hf], 2);
                    l_[mf][hf] = l_[mf][hf]*cr[mf][hf] + rsum[mf][hf];
                }

            // ---- P @ V over this unit's 32 keys ----
#pragma unroll
            for (int j = 0; j < 2; j++) {
                uint32_t pf[2][4];
#pragma unroll
                for (int mf = 0; mf < 2; mf++)
#pragma unroll
                    for (int half = 0; half < 2; half++) {
                        const int nf = 2*j + half;
#pragma unroll
                        for (int rr = 0; rr < 2; rr++) {
                            __half2 hv = __floats2half2_rn(sb[mf][nf][rr*2], sb[mf][nf][rr*2+1]);
                            pf[mf][half*2 + rr] = *(uint32_t*)&hv;
                        }
                    }
                const int kg = u*2 + j;
#pragma unroll
                for (int g = 0; g < 4; g++) {
                    const uint32_t boff = SWZ128((uint32_t)((g*16 + brow)*128 + (kg*2 + bsel)*16));
                    uint32_t v4[4];
                    LDSM4(v4, so + 24576 + boff);
#pragma unroll
                    for (int sub = 0; sub < 2; sub++)
#pragma unroll
                        for (int mf = 0; mf < 2; mf++)
                            MMA_F16(O[mf][2*g + sub], pf[mf], v4[2*sub], v4[2*sub+1]);
                }
            }
        }
        __syncthreads();
    }

    // ---- epilogue: warp owns its rows fully, direct write ----
#pragma unroll
    for (int mf = 0; mf < 2; mf++)
#pragma unroll
        for (int hf = 0; hf < 2; hf++) {
            const int row = w*32 + mf*16 + hf*8 + rowq;
            const float il = 1.0f / l_[mf][hf];
            float* op = out + ((size_t)b_*SSQ + qb + row)*HD + h*DHD + (lane & 3)*2;
#pragma unroll
            for (int nf = 0; nf < 8; nf++)
                *(float2*)(op + nf*8) = make_float2(O[mf][nf][hf*2]*il, O[mf][nf][hf*2+1]*il);
        }
}

// ---------------------------------------------------------------------------
extern "C" void kernel_launch(void* const* d_in, const int* in_sizes, int n_in,
                              void* d_out, int out_size)
{
    const float* hs   = (const float*)d_in[0];
    const float* te   = (const float*)d_in[1];
    const float* se   = (const float*)d_in[2];
    const float* mask = (const float*)d_in[3];
    const float* Wq = (const float*)d_in[4];  const float* bq = (const float*)d_in[5];
    const float* Wk = (const float*)d_in[6];  const float* bk = (const float*)d_in[7];
    const float* Wv = (const float*)d_in[8];  const float* bv = (const float*)d_in[9];
    const float* Wt = (const float*)d_in[10]; const float* bt = (const float*)d_in[11];
    const float* Ws = (const float*)d_in[12]; const float* bs = (const float*)d_in[13];
    float* out = (float*)d_out;

    dim3 gx((BB*SSQ*HD)/4/256, 3);
    split_x_kernel<<<gx, 256>>>(hs, te, se);
    dim3 gw((HD*HD)/4/256, 5);
    split_w_kernel<<<gw, 256>>>(Wq, Wk, Wv, Wt, Ws);

    cudaFuncSetAttribute(proj_hmma_kernel, cudaFuncAttributeMaxDynamicSharedMemorySize, PROJ_SMEM);
    dim3 gp(HD/128, (BB*SSQ)/128, 5);   // (6, 32, 5)
    proj_hmma_kernel<<<gp, 256, PROJ_SMEM>>>(bq, bk, bv, bt, bs);

    cudaFuncSetAttribute(attn_hmma_kernel, cudaFuncAttributeMaxDynamicSharedMemorySize, ATTN_SMEM);
    dim3 ga(SSQ/128, BB*NHD);           // (8, 48)
    attn_hmma_kernel<<<ga, 128, ATTN_SMEM>>>(mask, out);
}